// round 14
// baseline (speedup 1.0000x reference)
#include <cuda_runtime.h>
#include <cstdint>

// out = clip(low_img * c[b,c], 1e-8, 1) ** (mask==0 ? g1[b,c] : g2[b,c])
// B=16, C=3, H=512, W=512 -> 12,582,912 elems. ~150 MB irreducible traffic.
// Final form: exact-cover branchless body, front-batched .cs loads,
// write-through stores, with o0's store issued before o1's compute
// (drain write path overlapped with second MUFU chain).
// Measured ceiling: ~5.6 TB/s (~71% HBM) for this 2:1 R/W streaming mix.

#define HW_LOG2_VEC4 16   // (H*W)/4 = 65536 vec4 per (b,c) plane

__device__ __forceinline__ float fast_lg2(float x) {
    float y; asm("lg2.approx.f32 %0, %1;" : "=f"(y) : "f"(x)); return y;
}
__device__ __forceinline__ float fast_ex2(float x) {
    float y; asm("ex2.approx.f32 %0, %1;" : "=f"(y) : "f"(x)); return y;
}

__device__ __forceinline__ float4 ld4_cs(const float4* p) {
    float4 v;
    asm("ld.global.cs.nc.v4.f32 {%0,%1,%2,%3}, [%4];"
        : "=f"(v.x), "=f"(v.y), "=f"(v.z), "=f"(v.w) : "l"(p));
    return v;
}
__device__ __forceinline__ int4 ldi4_cs(const int4* p) {
    int4 v;
    asm("ld.global.cs.nc.v4.s32 {%0,%1,%2,%3}, [%4];"
        : "=r"(v.x), "=r"(v.y), "=r"(v.z), "=r"(v.w) : "l"(p));
    return v;
}
__device__ __forceinline__ void st4_wt(float4* p, float4 v) {
    asm volatile("st.global.wt.v4.f32 [%0], {%1,%2,%3,%4};"
                 :: "l"(p), "f"(v.x), "f"(v.y), "f"(v.z), "f"(v.w) : "memory");
}

__device__ __forceinline__ float apply_one(float x, int m, float cc, float G1, float G2) {
    float t = fminf(fmaxf(x * cc, 1e-8f), 1.0f);
    float g = (m == 0) ? G1 : G2;
    return fast_ex2(g * fast_lg2(t));
}

__device__ __forceinline__ float4 apply_vec(float4 v, int4 m, int bc,
                                            const float* __restrict__ g1,
                                            const float* __restrict__ g2,
                                            const float* __restrict__ c) {
    float cc = __ldg(c  + bc);
    float G1 = __ldg(g1 + bc);
    float G2 = __ldg(g2 + bc);
    float4 o;
    o.x = apply_one(v.x, m.x, cc, G1, G2);
    o.y = apply_one(v.y, m.y, cc, G1, G2);
    o.z = apply_one(v.z, m.z, cc, G1, G2);
    o.w = apply_one(v.w, m.w, cc, G1, G2);
    return o;
}

// Hot path: exact cover guaranteed by the launcher — no bounds checks.
__global__ void __launch_bounds__(256)
net_gamma_kernel_exact(const float4* __restrict__ low,
                       const int4*   __restrict__ mask,
                       const float*  __restrict__ g1,
                       const float*  __restrict__ g2,
                       const float*  __restrict__ c,
                       float4*       __restrict__ out)
{
    int i0 = blockIdx.x * (blockDim.x * 2) + threadIdx.x;
    int i1 = i0 + blockDim.x;

    // Front-batch all 4 global loads (64 B in flight per thread).
    float4 v0 = ld4_cs(low  + i0);
    float4 v1 = ld4_cs(low  + i1);
    int4   m0 = ldi4_cs(mask + i0);
    int4   m1 = ldi4_cs(mask + i1);

    // Compute+store i0 first, then i1: first STG issues early and drains
    // overlapped with the second MUFU chain.
    float4 o0 = apply_vec(v0, m0, i0 >> HW_LOG2_VEC4, g1, g2, c);
    st4_wt(out + i0, o0);

    float4 o1 = apply_vec(v1, m1, i1 >> HW_LOG2_VEC4, g1, g2, c);
    st4_wt(out + i1, o1);
}

// Guarded fallback (only used if the shape ever changes).
__global__ void __launch_bounds__(256)
net_gamma_kernel_guard(const float4* __restrict__ low,
                       const int4*   __restrict__ mask,
                       const float*  __restrict__ g1,
                       const float*  __restrict__ g2,
                       const float*  __restrict__ c,
                       float4*       __restrict__ out,
                       int n4)
{
    int i0 = blockIdx.x * (blockDim.x * 2) + threadIdx.x;
    int i1 = i0 + blockDim.x;

    if (i1 < n4) {
        float4 v0 = ld4_cs(low  + i0);
        float4 v1 = ld4_cs(low  + i1);
        int4   m0 = ldi4_cs(mask + i0);
        int4   m1 = ldi4_cs(mask + i1);
        float4 o0 = apply_vec(v0, m0, i0 >> HW_LOG2_VEC4, g1, g2, c);
        st4_wt(out + i0, o0);
        float4 o1 = apply_vec(v1, m1, i1 >> HW_LOG2_VEC4, g1, g2, c);
        st4_wt(out + i1, o1);
    } else if (i0 < n4) {
        float4 v0 = ld4_cs(low  + i0);
        int4   m0 = ldi4_cs(mask + i0);
        st4_wt(out + i0, apply_vec(v0, m0, i0 >> HW_LOG2_VEC4, g1, g2, c));
    }
}

extern "C" void kernel_launch(void* const* d_in, const int* in_sizes, int n_in,
                              void* d_out, int out_size)
{
    const float4* low  = (const float4*)d_in[0];
    const float*  g1   = (const float*)d_in[1];
    const float*  g2   = (const float*)d_in[2];
    const float*  c    = (const float*)d_in[3];
    const int4*   mask = (const int4*)d_in[4];
    float4* out = (float4*)d_out;

    int n4 = out_size / 4;                  // 3,145,728 for this problem
    int threads = 256;
    int per_block = threads * 2;            // 512 vec4 per block
    int blocks = (n4 + per_block - 1) / per_block;

    if ((out_size & 3) == 0 && n4 % per_block == 0) {
        // Exact cover: branchless hot path (always taken for this shape).
        net_gamma_kernel_exact<<<blocks, threads>>>(low, mask, g1, g2, c, out);
    } else {
        net_gamma_kernel_guard<<<blocks, threads>>>(low, mask, g1, g2, c, out, n4);
    }
}

// round 15
// speedup vs baseline: 1.0109x; 1.0109x over previous
#include <cuda_runtime.h>
#include <cstdint>

// out = clip(low_img * c[b,c], 1e-8, 1) ** (mask==0 ? g1[b,c] : g2[b,c])
// B=16, C=3, H=512, W=512 -> 12,582,912 elems. ~150 MB irreducible traffic.
// FINAL (= R13, measured best: 23.65us bench / 19.26us kernel, 5.62 TB/s):
//   - exact-cover branchless hot path (n4 = 6144 blocks * 512 vec4)
//   - all 4 global loads front-batched (64 B in flight per thread)
//   - loads:  ld.global.cs.nc.v4 (evict-first; best-measured)
//   - stores: st.global.wt.v4    (write-through; best-measured)
//   - both stores after both compute chains (R14 reorder regressed)
// Measured ceiling: ~5.6 TB/s (~71% HBM) for this 2:1 R/W streaming mix.

#define HW_LOG2_VEC4 16   // (H*W)/4 = 65536 vec4 per (b,c) plane

__device__ __forceinline__ float fast_lg2(float x) {
    float y; asm("lg2.approx.f32 %0, %1;" : "=f"(y) : "f"(x)); return y;
}
__device__ __forceinline__ float fast_ex2(float x) {
    float y; asm("ex2.approx.f32 %0, %1;" : "=f"(y) : "f"(x)); return y;
}

__device__ __forceinline__ float4 ld4_cs(const float4* p) {
    float4 v;
    asm("ld.global.cs.nc.v4.f32 {%0,%1,%2,%3}, [%4];"
        : "=f"(v.x), "=f"(v.y), "=f"(v.z), "=f"(v.w) : "l"(p));
    return v;
}
__device__ __forceinline__ int4 ldi4_cs(const int4* p) {
    int4 v;
    asm("ld.global.cs.nc.v4.s32 {%0,%1,%2,%3}, [%4];"
        : "=r"(v.x), "=r"(v.y), "=r"(v.z), "=r"(v.w) : "l"(p));
    return v;
}
__device__ __forceinline__ void st4_wt(float4* p, float4 v) {
    asm volatile("st.global.wt.v4.f32 [%0], {%1,%2,%3,%4};"
                 :: "l"(p), "f"(v.x), "f"(v.y), "f"(v.z), "f"(v.w) : "memory");
}

__device__ __forceinline__ float apply_one(float x, int m, float cc, float G1, float G2) {
    float t = fminf(fmaxf(x * cc, 1e-8f), 1.0f);
    float g = (m == 0) ? G1 : G2;
    return fast_ex2(g * fast_lg2(t));
}

__device__ __forceinline__ float4 apply_vec(float4 v, int4 m, int bc,
                                            const float* __restrict__ g1,
                                            const float* __restrict__ g2,
                                            const float* __restrict__ c) {
    float cc = __ldg(c  + bc);
    float G1 = __ldg(g1 + bc);
    float G2 = __ldg(g2 + bc);
    float4 o;
    o.x = apply_one(v.x, m.x, cc, G1, G2);
    o.y = apply_one(v.y, m.y, cc, G1, G2);
    o.z = apply_one(v.z, m.z, cc, G1, G2);
    o.w = apply_one(v.w, m.w, cc, G1, G2);
    return o;
}

// Hot path: exact cover guaranteed by the launcher — no bounds checks.
__global__ void __launch_bounds__(256)
net_gamma_kernel_exact(const float4* __restrict__ low,
                       const int4*   __restrict__ mask,
                       const float*  __restrict__ g1,
                       const float*  __restrict__ g2,
                       const float*  __restrict__ c,
                       float4*       __restrict__ out)
{
    int i0 = blockIdx.x * (blockDim.x * 2) + threadIdx.x;
    int i1 = i0 + blockDim.x;

    // Front-batch all 4 global loads (64 B in flight per thread).
    float4 v0 = ld4_cs(low  + i0);
    float4 v1 = ld4_cs(low  + i1);
    int4   m0 = ldi4_cs(mask + i0);
    int4   m1 = ldi4_cs(mask + i1);

    float4 o0 = apply_vec(v0, m0, i0 >> HW_LOG2_VEC4, g1, g2, c);
    float4 o1 = apply_vec(v1, m1, i1 >> HW_LOG2_VEC4, g1, g2, c);

    st4_wt(out + i0, o0);
    st4_wt(out + i1, o1);
}

// Guarded fallback (only used if the shape ever changes).
__global__ void __launch_bounds__(256)
net_gamma_kernel_guard(const float4* __restrict__ low,
                       const int4*   __restrict__ mask,
                       const float*  __restrict__ g1,
                       const float*  __restrict__ g2,
                       const float*  __restrict__ c,
                       float4*       __restrict__ out,
                       int n4)
{
    int i0 = blockIdx.x * (blockDim.x * 2) + threadIdx.x;
    int i1 = i0 + blockDim.x;

    if (i1 < n4) {
        float4 v0 = ld4_cs(low  + i0);
        float4 v1 = ld4_cs(low  + i1);
        int4   m0 = ldi4_cs(mask + i0);
        int4   m1 = ldi4_cs(mask + i1);
        float4 o0 = apply_vec(v0, m0, i0 >> HW_LOG2_VEC4, g1, g2, c);
        float4 o1 = apply_vec(v1, m1, i1 >> HW_LOG2_VEC4, g1, g2, c);
        st4_wt(out + i0, o0);
        st4_wt(out + i1, o1);
    } else if (i0 < n4) {
        float4 v0 = ld4_cs(low  + i0);
        int4   m0 = ldi4_cs(mask + i0);
        st4_wt(out + i0, apply_vec(v0, m0, i0 >> HW_LOG2_VEC4, g1, g2, c));
    }
}

extern "C" void kernel_launch(void* const* d_in, const int* in_sizes, int n_in,
                              void* d_out, int out_size)
{
    const float4* low  = (const float4*)d_in[0];
    const float*  g1   = (const float*)d_in[1];
    const float*  g2   = (const float*)d_in[2];
    const float*  c    = (const float*)d_in[3];
    const int4*   mask = (const int4*)d_in[4];
    float4* out = (float4*)d_out;

    int n4 = out_size / 4;                  // 3,145,728 for this problem
    int threads = 256;
    int per_block = threads * 2;            // 512 vec4 per block
    int blocks = (n4 + per_block - 1) / per_block;

    if ((out_size & 3) == 0 && n4 % per_block == 0) {
        // Exact cover: branchless hot path (always taken for this shape).
        net_gamma_kernel_exact<<<blocks, threads>>>(low, mask, g1, g2, c, out);
    } else {
        net_gamma_kernel_guard<<<blocks, threads>>>(low, mask, g1, g2, c, out, n4);
    }
}

// round 17
// speedup vs baseline: 1.0334x; 1.0223x over previous
#include <cuda_runtime.h>
#include <cstdint>

// out = clip(low_img * c[b,c], 1e-8, 1) ** (mask==0 ? g1[b,c] : g2[b,c])
// B=16, C=3, H=512, W=512 -> 12,582,912 elems. ~150 MB irreducible traffic.
// FINAL: R13/R15 config (measured best, 23.52us bench) with load order
// v0,m0,v1,m1 (first compute chain's deps retire earliest; all 4 loads
// still front-batched).
//   loads:  ld.global.cs.nc.v4 (evict-first; best-measured)
//   stores: st.global.wt.v4    (write-through; best-measured)
// Measured ceiling: ~5.6 TB/s (~70% HBM) for this 2:1 R/W streaming mix.

#define HW_LOG2_VEC4 16   // (H*W)/4 = 65536 vec4 per (b,c) plane

__device__ __forceinline__ float fast_lg2(float x) {
    float y; asm("lg2.approx.f32 %0, %1;" : "=f"(y) : "f"(x)); return y;
}
__device__ __forceinline__ float fast_ex2(float x) {
    float y; asm("ex2.approx.f32 %0, %1;" : "=f"(y) : "f"(x)); return y;
}

__device__ __forceinline__ float4 ld4_cs(const float4* p) {
    float4 v;
    asm("ld.global.cs.nc.v4.f32 {%0,%1,%2,%3}, [%4];"
        : "=f"(v.x), "=f"(v.y), "=f"(v.z), "=f"(v.w) : "l"(p));
    return v;
}
__device__ __forceinline__ int4 ldi4_cs(const int4* p) {
    int4 v;
    asm("ld.global.cs.nc.v4.s32 {%0,%1,%2,%3}, [%4];"
        : "=r"(v.x), "=r"(v.y), "=r"(v.z), "=r"(v.w) : "l"(p));
    return v;
}
__device__ __forceinline__ void st4_wt(float4* p, float4 v) {
    asm volatile("st.global.wt.v4.f32 [%0], {%1,%2,%3,%4};"
                 :: "l"(p), "f"(v.x), "f"(v.y), "f"(v.z), "f"(v.w) : "memory");
}

__device__ __forceinline__ float apply_one(float x, int m, float cc, float G1, float G2) {
    float t = fminf(fmaxf(x * cc, 1e-8f), 1.0f);
    float g = (m == 0) ? G1 : G2;
    return fast_ex2(g * fast_lg2(t));
}

__device__ __forceinline__ float4 apply_vec(float4 v, int4 m, int bc,
                                            const float* __restrict__ g1,
                                            const float* __restrict__ g2,
                                            const float* __restrict__ c) {
    float cc = __ldg(c  + bc);
    float G1 = __ldg(g1 + bc);
    float G2 = __ldg(g2 + bc);
    float4 o;
    o.x = apply_one(v.x, m.x, cc, G1, G2);
    o.y = apply_one(v.y, m.y, cc, G1, G2);
    o.z = apply_one(v.z, m.z, cc, G1, G2);
    o.w = apply_one(v.w, m.w, cc, G1, G2);
    return o;
}

// Hot path: exact cover guaranteed by the launcher — no bounds checks.
__global__ void __launch_bounds__(256)
net_gamma_kernel_exact(const float4* __restrict__ low,
                       const int4*   __restrict__ mask,
                       const float*  __restrict__ g1,
                       const float*  __restrict__ g2,
                       const float*  __restrict__ c,
                       float4*       __restrict__ out)
{
    int i0 = blockIdx.x * (blockDim.x * 2) + threadIdx.x;
    int i1 = i0 + blockDim.x;

    // Front-batch all 4 global loads; first chain's deps (v0,m0) issue first.
    float4 v0 = ld4_cs(low  + i0);
    int4   m0 = ldi4_cs(mask + i0);
    float4 v1 = ld4_cs(low  + i1);
    int4   m1 = ldi4_cs(mask + i1);

    float4 o0 = apply_vec(v0, m0, i0 >> HW_LOG2_VEC4, g1, g2, c);
    float4 o1 = apply_vec(v1, m1, i1 >> HW_LOG2_VEC4, g1, g2, c);

    st4_wt(out + i0, o0);
    st4_wt(out + i1, o1);
}

// Guarded fallback (only used if the shape ever changes).
__global__ void __launch_bounds__(256)
net_gamma_kernel_guard(const float4* __restrict__ low,
                       const int4*   __restrict__ mask,
                       const float*  __restrict__ g1,
                       const float*  __restrict__ g2,
                       const float*  __restrict__ c,
                       float4*       __restrict__ out,
                       int n4)
{
    int i0 = blockIdx.x * (blockDim.x * 2) + threadIdx.x;
    int i1 = i0 + blockDim.x;

    if (i1 < n4) {
        float4 v0 = ld4_cs(low  + i0);
        int4   m0 = ldi4_cs(mask + i0);
        float4 v1 = ld4_cs(low  + i1);
        int4   m1 = ldi4_cs(mask + i1);
        float4 o0 = apply_vec(v0, m0, i0 >> HW_LOG2_VEC4, g1, g2, c);
        float4 o1 = apply_vec(v1, m1, i1 >> HW_LOG2_VEC4, g1, g2, c);
        st4_wt(out + i0, o0);
        st4_wt(out + i1, o1);
    } else if (i0 < n4) {
        float4 v0 = ld4_cs(low  + i0);
        int4   m0 = ldi4_cs(mask + i0);
        st4_wt(out + i0, apply_vec(v0, m0, i0 >> HW_LOG2_VEC4, g1, g2, c));
    }
}

extern "C" void kernel_launch(void* const* d_in, const int* in_sizes, int n_in,
                              void* d_out, int out_size)
{
    const float4* low  = (const float4*)d_in[0];
    const float*  g1   = (const float*)d_in[1];
    const float*  g2   = (const float*)d_in[2];
    const float*  c    = (const float*)d_in[3];
    const int4*   mask = (const int4*)d_in[4];
    float4* out = (float4*)d_out;

    int n4 = out_size / 4;                  // 3,145,728 for this problem
    int threads = 256;
    int per_block = threads * 2;            // 512 vec4 per block
    int blocks = (n4 + per_block - 1) / per_block;

    if ((out_size & 3) == 0 && n4 % per_block == 0) {
        // Exact cover: branchless hot path (always taken for this shape).
        net_gamma_kernel_exact<<<blocks, threads>>>(low, mask, g1, g2, c, out);
    } else {
        net_gamma_kernel_guard<<<blocks, threads>>>(low, mask, g1, g2, c, out, n4);
    }
}